// round 5
// baseline (speedup 1.0000x reference)
#include <cuda_runtime.h>
#include <stdint.h>

// Problem constants
#define NUM_BOXES    512
#define NUM_COORDS   200000
#define FEAT_C       128
#define MAX_SELECTED 262144
#define N_ELEMS      (NUM_BOXES * NUM_COORDS)   // 102,400,000 mask elements
#define THREADS      256
#define ELEMS_PER_TH 16
#define ELEMS_PER_BLK (THREADS * ELEMS_PER_TH)  // 4096
#define NBLK         (N_ELEMS / ELEMS_PER_BLK)  // 25000 exactly

// Scratch (device globals — no allocation allowed)
__device__ int g_partials[NBLK];
__device__ int g_offsets[NBLK];
__device__ int g_count;
__device__ int g_selidx[MAX_SELECTED];
__device__ unsigned g_nonconform = 0;  // 1 => mask is byte-bools; 0 => 32-bit elems

// ---------------------------------------------------------------------------
// Mode detection: scan first 1M words. 32-bit-element masks contain only
// {0, 1, 0x3F800000}; byte-bool masks produce words with nonzero high lanes.
// Pure function of input -> deterministic across graph replays.
// ---------------------------------------------------------------------------
__global__ void k_detect(const unsigned* __restrict__ w) {
    unsigned idx = blockIdx.x * blockDim.x + threadIdx.x;
    unsigned stride = gridDim.x * blockDim.x;
    unsigned bad = 0;
    for (unsigned i = idx; i < (1u << 20); i += stride) {
        unsigned v = w[i];
        if (v != 0u && v != 1u && v != 0x3F800000u) bad = 1u;
    }
    if (bad) g_nonconform = 1u;   // benign race: all writers store 1
}

// Per-thread element-count helper. Loads the thread's 16 elements and returns
// count. In byte mode elements are 0/1 bytes (dp4a); in word mode, nonzero words.
__device__ __forceinline__ int load_count(const void* mask, int blk, int tid,
                                          int byte_mode, uint4 v[4]) {
    if (byte_mode) {
        v[0] = ((const uint4*)mask)[(size_t)blk * 256 + tid];  // 16 bytes
        unsigned a = 0;
        a = __dp4a(v[0].x, 0x01010101u, a);
        a = __dp4a(v[0].y, 0x01010101u, a);
        a = __dp4a(v[0].z, 0x01010101u, a);
        a = __dp4a(v[0].w, 0x01010101u, a);
        return (int)a;
    } else {
        const uint4* p = (const uint4*)mask + (size_t)blk * 1024 + (size_t)tid * 4;
        int c = 0;
#pragma unroll
        for (int i = 0; i < 4; i++) {
            v[i] = p[i];                                        // 16 words
            c += (v[i].x != 0u) + (v[i].y != 0u) + (v[i].z != 0u) + (v[i].w != 0u);
        }
        return c;
    }
}

// ---------------------------------------------------------------------------
// Pass 1: per-block count
// ---------------------------------------------------------------------------
__global__ void k_count(const void* __restrict__ mask) {
    const int blk = blockIdx.x, tid = threadIdx.x;
    const int byte_mode = (g_nonconform != 0u);
    uint4 v[4];
    int s = load_count(mask, blk, tid, byte_mode, v);
#pragma unroll
    for (int o = 16; o; o >>= 1) s += __shfl_down_sync(0xFFFFFFFFu, s, o);
    __shared__ int ws[8];
    if ((tid & 31) == 0) ws[tid >> 5] = s;
    __syncthreads();
    if (tid < 8) {
        int t = ws[tid];
#pragma unroll
        for (int o = 4; o; o >>= 1) t += __shfl_down_sync(0xFFu, t, o);
        if (tid == 0) g_partials[blk] = t;
    }
}

// ---------------------------------------------------------------------------
// Pass 2: single-block exclusive scan of 25000 partials
// ---------------------------------------------------------------------------
__global__ void k_scan() {
    __shared__ int sh[1024];
    const int tid = threadIdx.x;
    int carry = 0;
    for (int base = 0; base < NBLK; base += 1024) {
        int i = base + tid;
        int v = (i < NBLK) ? g_partials[i] : 0;
        sh[tid] = v;
        __syncthreads();
#pragma unroll
        for (int off = 1; off < 1024; off <<= 1) {
            int t = (tid >= off) ? sh[tid - off] : 0;
            __syncthreads();
            sh[tid] += t;
            __syncthreads();
        }
        int incl = sh[tid];
        if (i < NBLK) g_offsets[i] = carry + incl - v;  // exclusive
        __syncthreads();
        carry += sh[1023];
        __syncthreads();
    }
    if (tid == 0) g_count = carry;
}

// ---------------------------------------------------------------------------
// Pass 3: ordered emit. Coords written as FLOAT VALUES [x,y,z,box].
// ---------------------------------------------------------------------------
__global__ void k_emit(const void* __restrict__ mask,
                       const int4* __restrict__ coords,
                       float4* __restrict__ out_ext) {
    const int blk = blockIdx.x, tid = threadIdx.x;
    const int lane = tid & 31, wrp = tid >> 5;
    const int byte_mode = (g_nonconform != 0u);

    uint4 v[4];
    int cnt = load_count(mask, blk, tid, byte_mode, v);

    int incl = cnt;
#pragma unroll
    for (int o = 1; o < 32; o <<= 1) {
        int t = __shfl_up_sync(0xFFFFFFFFu, incl, o);
        if (lane >= o) incl += t;
    }
    __shared__ int ws[8];
    if (lane == 31) ws[wrp] = incl;
    __syncthreads();
    int wbase = 0;
#pragma unroll
    for (int i = 0; i < 8; i++) wbase += (i < wrp) ? ws[i] : 0;

    int pout = g_offsets[blk] + wbase + (incl - cnt);
    const int ebase = blk * ELEMS_PER_BLK + tid * ELEMS_PER_TH;

    auto emit_one = [&](int elem) {
        if (pout < MAX_SELECTED) {
            int coord = elem % NUM_COORDS;
            int box   = elem / NUM_COORDS;
            g_selidx[pout] = coord;
            int4 c = coords[coord];
            out_ext[pout] = make_float4((float)c.x, (float)c.y,
                                        (float)c.z, (float)box);
        }
        pout++;
    };

    if (byte_mode) {
        unsigned words[4] = { v[0].x, v[0].y, v[0].z, v[0].w };
#pragma unroll
        for (int j = 0; j < 4; j++) {
            unsigned w32 = words[j];
            if (w32 == 0u) continue;
#pragma unroll
            for (int b = 0; b < 4; b++)
                if ((w32 >> (8 * b)) & 0xFFu) emit_one(ebase + j * 4 + b);
        }
    } else {
#pragma unroll
        for (int i = 0; i < 4; i++) {
            unsigned words[4] = { v[i].x, v[i].y, v[i].z, v[i].w };
#pragma unroll
            for (int j = 0; j < 4; j++)
                if (words[j] != 0u) emit_one(ebase + i * 4 + j);
        }
    }
}

// ---------------------------------------------------------------------------
// Pass 4: warp-per-row feature gather + zero tail
// ---------------------------------------------------------------------------
__global__ void k_gather(const float4* __restrict__ feat,
                         float4* __restrict__ out_ext,
                         float4* __restrict__ out_feat) {
    const int gw   = (int)((blockIdx.x * (unsigned)blockDim.x + threadIdx.x) >> 5);
    const int lane = threadIdx.x & 31;
    if (gw >= MAX_SELECTED) return;
    if (gw < g_count) {
        int c = g_selidx[gw];
        out_feat[(size_t)gw * 32 + lane] = feat[(size_t)c * 32 + lane];
    } else {
        out_feat[(size_t)gw * 32 + lane] = make_float4(0.f, 0.f, 0.f, 0.f);
        if (lane == 0) out_ext[gw] = make_float4(0.f, 0.f, 0.f, 0.f);
    }
}

// ---------------------------------------------------------------------------
extern "C" void kernel_launch(void* const* d_in, const int* in_sizes, int n_in,
                              void* d_out, int out_size) {
    const int4*   coords = nullptr;
    const float4* feat   = nullptr;
    const void*   mask   = nullptr;
    for (int i = 0; i < n_in; i++) {
        if (in_sizes[i] == NUM_COORDS * 4)           coords = (const int4*)d_in[i];
        else if (in_sizes[i] == NUM_COORDS * FEAT_C) feat   = (const float4*)d_in[i];
        else if (in_sizes[i] == N_ELEMS)             mask   = d_in[i];
    }
    (void)out_size;

    float* out = (float*)d_out;
    float4* out_ext  = (float4*)out;                              // [262144,4] as floats
    float4* out_feat = (float4*)(out + 4 * (size_t)MAX_SELECTED); // [262144,128]

    k_detect<<<256, 256>>>((const unsigned*)mask);
    k_count<<<NBLK, THREADS>>>(mask);
    k_scan<<<1, 1024>>>();
    k_emit<<<NBLK, THREADS>>>(mask, coords, out_ext);
    k_gather<<<MAX_SELECTED * 32 / 256, 256>>>(feat, out_ext, out_feat);
}

// round 6
// speedup vs baseline: 1.2845x; 1.2845x over previous
#include <cuda_runtime.h>
#include <stdint.h>

// Problem constants
#define NUM_BOXES    512
#define NUM_COORDS   200000
#define FEAT_C       128
#define MAX_SELECTED 262144
#define N_ELEMS      (NUM_BOXES * NUM_COORDS)   // 102,400,000 mask elements
#define THREADS      256
#define ELEMS_PER_TH 16
#define ELEMS_PER_BLK (THREADS * ELEMS_PER_TH)  // 4096
#define NBLK         (N_ELEMS / ELEMS_PER_BLK)  // 25000 exactly

// Decoupled-lookback descriptor: bits 31:30 flag, bits 29:0 value.
#define FLAG_INVALID 0u
#define FLAG_AGG     (1u << 30)
#define FLAG_PREFIX  (2u << 30)
#define VAL_MASK     0x3FFFFFFFu

// Scratch (device globals — no allocation allowed)
__device__ unsigned g_desc[NBLK];
__device__ int g_count;
__device__ int g_selidx[MAX_SELECTED];
__device__ unsigned g_nonconform = 0;  // 1 => mask is byte-bools; 0 => 32-bit elems

// ---------------------------------------------------------------------------
// Init: zero lookback descriptors (required every graph replay).
// ---------------------------------------------------------------------------
__global__ void k_init() {
    int i = blockIdx.x * blockDim.x + threadIdx.x;
    if (i < NBLK) g_desc[i] = FLAG_INVALID;
}

// ---------------------------------------------------------------------------
// Mode detection: word-mode masks contain only {0, 1, 0x3F800000}.
// Monotone (only ever sets 1) and input-determined -> replay-safe w/o reset.
// ---------------------------------------------------------------------------
__global__ void k_detect(const unsigned* __restrict__ w) {
    unsigned idx = blockIdx.x * blockDim.x + threadIdx.x;
    unsigned stride = gridDim.x * blockDim.x;
    unsigned bad = 0;
    for (unsigned i = idx; i < (1u << 20); i += stride) {
        unsigned v = w[i];
        if (v != 0u && v != 1u && v != 0x3F800000u) bad = 1u;
    }
    if (bad) g_nonconform = 1u;
}

// Load the thread's 16 contiguous elements; return count of set elements.
__device__ __forceinline__ int load_count(const void* mask, int blk, int tid,
                                          int byte_mode, uint4 v[4]) {
    if (byte_mode) {
        v[0] = ((const uint4*)mask)[(size_t)blk * 256 + tid];  // 16 bytes
        unsigned a = 0;
        a = __dp4a(v[0].x, 0x01010101u, a);
        a = __dp4a(v[0].y, 0x01010101u, a);
        a = __dp4a(v[0].z, 0x01010101u, a);
        a = __dp4a(v[0].w, 0x01010101u, a);
        return (int)a;
    } else {
        const uint4* p = (const uint4*)mask + (size_t)blk * 1024 + (size_t)tid * 4;
        int c = 0;
#pragma unroll
        for (int i = 0; i < 4; i++) {
            v[i] = p[i];                                        // 16 words
            c += (v[i].x != 0u) + (v[i].y != 0u) + (v[i].z != 0u) + (v[i].w != 0u);
        }
        return c;
    }
}

// ---------------------------------------------------------------------------
// Fused single-pass: block scan + decoupled lookback + ordered emit.
// ---------------------------------------------------------------------------
__global__ void k_fused(const void* __restrict__ mask,
                        const int4* __restrict__ coords,
                        float4* __restrict__ out_ext) {
    const int blk = blockIdx.x, tid = threadIdx.x;
    const int lane = tid & 31, wrp = tid >> 5;
    const int byte_mode = (g_nonconform != 0u);

    uint4 v[4];
    int cnt = load_count(mask, blk, tid, byte_mode, v);

    // warp inclusive scan of per-thread counts
    int incl = cnt;
#pragma unroll
    for (int o = 1; o < 32; o <<= 1) {
        int t = __shfl_up_sync(0xFFFFFFFFu, incl, o);
        if (lane >= o) incl += t;
    }
    __shared__ int ws[8];
    __shared__ int s_excl;
    if (lane == 31) ws[wrp] = incl;
    __syncthreads();

    int wbase = 0, total = 0;
#pragma unroll
    for (int i = 0; i < 8; i++) {
        int w = ws[i];
        wbase += (i < wrp) ? w : 0;
        total += w;
    }

    // Publish this block's status
    if (tid == 0) {
        if (blk == 0) {
            atomicExch(&g_desc[0], FLAG_PREFIX | (unsigned)total);
            s_excl = 0;
            if (blk == NBLK - 1) g_count = total;
        } else {
            atomicExch(&g_desc[blk], FLAG_AGG | (unsigned)total);
        }
    }

    // Warp 0 lookback (32 predecessors per window, consumes partial progress)
    if (wrp == 0 && blk > 0) {
        int excl = 0;
        int k = blk - 1;
        while (true) {
            int idx = k - lane;
            unsigned s = (idx >= 0) ? atomicAdd(&g_desc[idx], 0u)
                                    : (FLAG_PREFIX | 0u);
            unsigned flag = s & 0xC0000000u;
            unsigned val  = s & VAL_MASK;
            unsigned bP = __ballot_sync(0xFFFFFFFFu, flag == FLAG_PREFIX);
            unsigned bI = __ballot_sync(0xFFFFFFFFu, flag == FLAG_INVALID);
            int firstP = bP ? (__ffs(bP) - 1) : 32;
            int firstI = bI ? (__ffs(bI) - 1) : 32;

            if (firstP < firstI) {
                // aggregates up to firstP-1, prefix at firstP: done
                unsigned contrib = (lane <= firstP) ? val : 0u;
#pragma unroll
                for (int o = 16; o; o >>= 1)
                    contrib += __shfl_xor_sync(0xFFFFFFFFu, contrib, o);
                excl += (int)contrib;
                break;
            } else if (firstI > 0) {
                // consume aggregates below the first invalid, keep waiting
                unsigned contrib = (lane < firstI) ? val : 0u;
#pragma unroll
                for (int o = 16; o; o >>= 1)
                    contrib += __shfl_xor_sync(0xFFFFFFFFu, contrib, o);
                excl += (int)contrib;
                k -= firstI;
            } else {
                __nanosleep(60);
            }
        }
        if (lane == 0) {
            s_excl = excl;
            atomicExch(&g_desc[blk], FLAG_PREFIX | (unsigned)(excl + total));
            if (blk == NBLK - 1) g_count = excl + total;
        }
    }
    __syncthreads();

    int pout = s_excl + wbase + (incl - cnt);
    const int ebase = blk * ELEMS_PER_BLK + tid * ELEMS_PER_TH;

    auto emit_one = [&](int elem) {
        if (pout < MAX_SELECTED) {
            int coord = elem % NUM_COORDS;
            int box   = elem / NUM_COORDS;
            g_selidx[pout] = coord;
            int4 c = coords[coord];
            out_ext[pout] = make_float4((float)c.x, (float)c.y,
                                        (float)c.z, (float)box);
        }
        pout++;
    };

    if (byte_mode) {
        unsigned words[4] = { v[0].x, v[0].y, v[0].z, v[0].w };
#pragma unroll
        for (int j = 0; j < 4; j++) {
            unsigned w32 = words[j];
            if (w32 == 0u) continue;
#pragma unroll
            for (int b = 0; b < 4; b++)
                if ((w32 >> (8 * b)) & 0xFFu) emit_one(ebase + j * 4 + b);
        }
    } else {
#pragma unroll
        for (int i = 0; i < 4; i++) {
            unsigned words[4] = { v[i].x, v[i].y, v[i].z, v[i].w };
#pragma unroll
            for (int j = 0; j < 4; j++)
                if (words[j] != 0u) emit_one(ebase + i * 4 + j);
        }
    }
}

// ---------------------------------------------------------------------------
// Feature gather: warp-per-row + zero tail
// ---------------------------------------------------------------------------
__global__ void k_gather(const float4* __restrict__ feat,
                         float4* __restrict__ out_ext,
                         float4* __restrict__ out_feat) {
    const int gw   = (int)((blockIdx.x * (unsigned)blockDim.x + threadIdx.x) >> 5);
    const int lane = threadIdx.x & 31;
    if (gw >= MAX_SELECTED) return;
    if (gw < g_count) {
        int c = g_selidx[gw];
        out_feat[(size_t)gw * 32 + lane] = feat[(size_t)c * 32 + lane];
    } else {
        out_feat[(size_t)gw * 32 + lane] = make_float4(0.f, 0.f, 0.f, 0.f);
        if (lane == 0) out_ext[gw] = make_float4(0.f, 0.f, 0.f, 0.f);
    }
}

// ---------------------------------------------------------------------------
extern "C" void kernel_launch(void* const* d_in, const int* in_sizes, int n_in,
                              void* d_out, int out_size) {
    const int4*   coords = nullptr;
    const float4* feat   = nullptr;
    const void*   mask   = nullptr;
    for (int i = 0; i < n_in; i++) {
        if (in_sizes[i] == NUM_COORDS * 4)           coords = (const int4*)d_in[i];
        else if (in_sizes[i] == NUM_COORDS * FEAT_C) feat   = (const float4*)d_in[i];
        else if (in_sizes[i] == N_ELEMS)             mask   = d_in[i];
    }
    (void)out_size;

    float* out = (float*)d_out;
    float4* out_ext  = (float4*)out;                              // [262144,4] as floats
    float4* out_feat = (float4*)(out + 4 * (size_t)MAX_SELECTED); // [262144,128]

    k_init<<<(NBLK + 255) / 256, 256>>>();
    k_detect<<<256, 256>>>((const unsigned*)mask);
    k_fused<<<NBLK, THREADS>>>(mask, coords, out_ext);
    k_gather<<<MAX_SELECTED * 32 / 256, 256>>>(feat, out_ext, out_feat);
}